// round 14
// baseline (speedup 1.0000x reference)
#include <cuda_runtime.h>
#include <cstdint>

#define BB 32
#define TT 8192
#define HH 256
#define CHUNK 128
#define NCH (TT / CHUNK)          // 64 chunks per batch
#define NSTAGE 2
#define SROWS 32
#define NSTG (CHUNK / SROWS)      // 4 stages per CTA
#define SBYTES (SROWS * HH * 4)   // 32 KB per stage

// Scratch (__device__ globals: allocation-free rule)
__device__ float g_vp[BB * 8 * HH];       // split-K partials of v
__device__ float g_scores[BB * TT];       // raw logits
__device__ float g_pm[BB * NCH];          // per-chunk max
__device__ float g_pl[BB * NCH];          // per-chunk sum-exp
__device__ float g_pc[BB * NCH * HH];     // per-chunk partial context

// ---------------- PDL helpers ----------------
__device__ __forceinline__ void gdc_wait() {
    asm volatile("griddepcontrol.wait;" ::: "memory");
}
__device__ __forceinline__ void gdc_launch() {
    asm volatile("griddepcontrol.launch_dependents;");
}

// ---------------- mbarrier / bulk-async helpers ----------------
__device__ __forceinline__ uint32_t smem_u32(const void* p) {
    return (uint32_t)__cvta_generic_to_shared(p);
}
__device__ __forceinline__ void mbar_init(uint32_t a, uint32_t cnt) {
    asm volatile("mbarrier.init.shared.b64 [%0], %1;" :: "r"(a), "r"(cnt) : "memory");
}
__device__ __forceinline__ void mbar_expect_tx(uint32_t a, uint32_t bytes) {
    asm volatile("mbarrier.arrive.expect_tx.shared.b64 _, [%0], %1;"
                 :: "r"(a), "r"(bytes) : "memory");
}
__device__ __forceinline__ void mbar_arrive(uint32_t a) {
    asm volatile("mbarrier.arrive.shared.b64 _, [%0];" :: "r"(a) : "memory");
}
__device__ __forceinline__ void mbar_wait(uint32_t a, uint32_t parity) {
    asm volatile(
        "{\n\t.reg .pred P;\n\t"
        "LAB_%=:\n\t"
        "mbarrier.try_wait.parity.shared.b64 P, [%0], %1;\n\t"
        "@P bra.uni DONE_%=;\n\t"
        "bra.uni LAB_%=;\n\t"
        "DONE_%=:\n\t}"
        :: "r"(a), "r"(parity) : "memory");
}
__device__ __forceinline__ void bulk_g2s(uint32_t dst, const void* src,
                                         uint32_t bytes, uint32_t mbar) {
    asm volatile(
        "cp.async.bulk.shared::cluster.global.mbarrier::complete_tx::bytes "
        "[%0], [%1], %2, [%3];"
        :: "r"(dst), "l"(src), "r"(bytes), "r"(mbar) : "memory");
}
__device__ __forceinline__ void prefetch_l2(const void* p) {
    asm volatile("prefetch.global.L2 [%0];" :: "l"(p));
}

// ---------------------------------------------------------------------------
// Kernel 0: split-K partial of v.  grid=(BB, 8), block=256.
// Signals dependents immediately so pass1 can start its hs prefetches.
// ---------------------------------------------------------------------------
__global__ void __launch_bounds__(256) vpart_kernel(const float* __restrict__ hs,
                                                    const float* __restrict__ W1) {
    gdc_launch();
    const int b = blockIdx.x;
    const int s = blockIdx.y;
    const int h = threadIdx.x;
    __shared__ float ht[32];
    if (h < 32)
        ht[h] = hs[(size_t)b * TT * HH + (size_t)(TT - 1) * HH + s * 32 + h];
    __syncthreads();
    float acc = 0.f;
#pragma unroll
    for (int o = 0; o < 32; o++)
        acc += W1[(s * 32 + o) * HH + h] * ht[o];
    g_vp[(b * 8 + s) * HH + h] = acc;
}

// ---------------------------------------------------------------------------
// Kernel 1: bulk-async-staged fused score + online softmax + partial context.
// grid=(NCH, BB)=2048 CTAs, block=256 (8 warps), 2-stage 32 KB dynamic-smem
// ring.  PDL: mbar init + TMA prefetch of hs BEFORE gdc_wait(); v read after.
// Consumer arrives on empty RIGHT AFTER its smem loads (before compute).
// ---------------------------------------------------------------------------
extern __shared__ __align__(16) float dynbuf[];   // NSTAGE * SROWS * HH floats

__global__ void __launch_bounds__(256) pass1_kernel(const float* __restrict__ hs) {
    __shared__ __align__(8) unsigned long long mb_full[NSTAGE];
    __shared__ __align__(8) unsigned long long mb_empty[NSTAGE];
    __shared__ float s_m[8], s_l[8];
    __shared__ float s_c[8][HH];                                  // 8 KB

    const int chunk = blockIdx.x;
    const int b = blockIdx.y;
    const int tid = threadIdx.x;
    const int w = tid >> 5;
    const int lane = tid & 31;

    uint32_t full_a[NSTAGE], empty_a[NSTAGE], buf_a[NSTAGE];
#pragma unroll
    for (int i = 0; i < NSTAGE; i++) {
        full_a[i] = smem_u32(&mb_full[i]);
        empty_a[i] = smem_u32(&mb_empty[i]);
        buf_a[i] = smem_u32(&dynbuf[i * SROWS * HH]);
    }

    if (tid == 0) {
#pragma unroll
        for (int i = 0; i < NSTAGE; i++) {
            mbar_init(full_a[i], 1);
            mbar_init(empty_a[i], 8);
        }
    }
    __syncthreads();

    const char* src =
        (const char*)(hs + ((size_t)b * TT + (size_t)chunk * CHUNK) * HH);

    if (tid == 0) {
#pragma unroll
        for (int i = 0; i < NSTAGE; i++) {
            mbar_expect_tx(full_a[i], SBYTES);
            bulk_g2s(buf_a[i], src + (size_t)i * SBYTES, SBYTES, full_a[i]);
        }
    }

    // Wait for vpart's grid (PDL) before touching g_vp.
    gdc_wait();

    // v slice for this lane = sum of the 8 split-K partials (L2-resident)
    const float4* vp4 = (const float4*)(g_vp) + (size_t)b * 8 * 64;
    float4 va = make_float4(0.f, 0.f, 0.f, 0.f);
    float4 vb = make_float4(0.f, 0.f, 0.f, 0.f);
#pragma unroll
    for (int s = 0; s < 8; s++) {
        float4 pa = vp4[s * 64 + lane];
        float4 pb = vp4[s * 64 + 32 + lane];
        va.x += pa.x; va.y += pa.y; va.z += pa.z; va.w += pa.w;
        vb.x += pb.x; vb.y += pb.y; vb.z += pb.z; vb.w += pb.w;
    }

    float m = -1e30f, l = 0.f;
    float4 ca = make_float4(0.f, 0.f, 0.f, 0.f);
    float4 cb = make_float4(0.f, 0.f, 0.f, 0.f);
    float* scores = g_scores + b * TT + chunk * CHUNK;

    for (int s = 0; s < NSTG; s++) {
        const int slot = s & (NSTAGE - 1);
        mbar_wait(full_a[slot], (s / NSTAGE) & 1);

        const float4* bf = (const float4*)(dynbuf + slot * SROWS * HH);
        const int r0 = w * 4;
        float4 x0a = bf[(r0 + 0) * 64 + lane], x0b = bf[(r0 + 0) * 64 + 32 + lane];
        float4 x1a = bf[(r0 + 1) * 64 + lane], x1b = bf[(r0 + 1) * 64 + 32 + lane];
        float4 x2a = bf[(r0 + 2) * 64 + lane], x2b = bf[(r0 + 2) * 64 + 32 + lane];
        float4 x3a = bf[(r0 + 3) * 64 + lane], x3b = bf[(r0 + 3) * 64 + 32 + lane];

        // Data is in registers — release the stage to the producer NOW.
        if (lane == 0) mbar_arrive(empty_a[slot]);

        float s0 = x0a.x * va.x + x0a.y * va.y + x0a.z * va.z + x0a.w * va.w
                 + x0b.x * vb.x + x0b.y * vb.y + x0b.z * vb.z + x0b.w * vb.w;
        float s1 = x1a.x * va.x + x1a.y * va.y + x1a.z * va.z + x1a.w * va.w
                 + x1b.x * vb.x + x1b.y * vb.y + x1b.z * vb.z + x1b.w * vb.w;
        float s2 = x2a.x * va.x + x2a.y * va.y + x2a.z * va.z + x2a.w * va.w
                 + x2b.x * vb.x + x2b.y * vb.y + x2b.z * vb.z + x2b.w * vb.w;
        float s3 = x3a.x * va.x + x3a.y * va.y + x3a.z * va.z + x3a.w * va.w
                 + x3b.x * vb.x + x3b.y * vb.y + x3b.z * vb.z + x3b.w * vb.w;
#pragma unroll
        for (int off = 16; off; off >>= 1) {
            s0 += __shfl_xor_sync(0xffffffffu, s0, off);
            s1 += __shfl_xor_sync(0xffffffffu, s1, off);
            s2 += __shfl_xor_sync(0xffffffffu, s2, off);
            s3 += __shfl_xor_sync(0xffffffffu, s3, off);
        }
        if (lane == 0)
            *(float4*)(scores + s * SROWS + r0) = make_float4(s0, s1, s2, s3);

        float mn = fmaxf(fmaxf(m, fmaxf(s0, s1)), fmaxf(s2, s3));
        float corr = __expf(m - mn);
        float p0 = __expf(s0 - mn);
        float p1 = __expf(s1 - mn);
        float p2 = __expf(s2 - mn);
        float p3 = __expf(s3 - mn);
        l = l * corr + p0 + p1 + p2 + p3;
        ca.x = ca.x * corr + p0 * x0a.x + p1 * x1a.x + p2 * x2a.x + p3 * x3a.x;
        ca.y = ca.y * corr + p0 * x0a.y + p1 * x1a.y + p2 * x2a.y + p3 * x3a.y;
        ca.z = ca.z * corr + p0 * x0a.z + p1 * x1a.z + p2 * x2a.z + p3 * x3a.z;
        ca.w = ca.w * corr + p0 * x0a.w + p1 * x1a.w + p2 * x2a.w + p3 * x3a.w;
        cb.x = cb.x * corr + p0 * x0b.x + p1 * x1b.x + p2 * x2b.x + p3 * x3b.x;
        cb.y = cb.y * corr + p0 * x0b.y + p1 * x1b.y + p2 * x2b.y + p3 * x3b.y;
        cb.z = cb.z * corr + p0 * x0b.z + p1 * x1b.z + p2 * x2b.z + p3 * x3b.z;
        cb.w = cb.w * corr + p0 * x0b.w + p1 * x1b.w + p2 * x2b.w + p3 * x3b.w;
        m = mn;

        if (tid == 0 && s + NSTAGE < NSTG) {
            const int ns = s + NSTAGE;
            mbar_wait(empty_a[slot], ((ns / NSTAGE) - 1) & 1);
            mbar_expect_tx(full_a[slot], SBYTES);
            bulk_g2s(buf_a[slot], src + (size_t)ns * SBYTES, SBYTES, full_a[slot]);
        }
    }

    gdc_launch();   // streaming done — let finish start ramping

    if (lane == 0) { s_m[w] = m; s_l[w] = l; }
    s_c[w][lane * 4 + 0] = ca.x;
    s_c[w][lane * 4 + 1] = ca.y;
    s_c[w][lane * 4 + 2] = ca.z;
    s_c[w][lane * 4 + 3] = ca.w;
    s_c[w][128 + lane * 4 + 0] = cb.x;
    s_c[w][128 + lane * 4 + 1] = cb.y;
    s_c[w][128 + lane * 4 + 2] = cb.z;
    s_c[w][128 + lane * 4 + 3] = cb.w;
    __syncthreads();

    float M = -1e30f;
#pragma unroll
    for (int ww = 0; ww < 8; ww++) M = fmaxf(M, s_m[ww]);
    float L = 0.f, C = 0.f;
#pragma unroll
    for (int ww = 0; ww < 8; ww++) {
        float e = __expf(s_m[ww] - M);
        L += s_l[ww] * e;
        C += s_c[ww][tid] * e;
    }
    const int pidx = b * NCH + chunk;
    g_pc[pidx * HH + tid] = C;
    if (tid == 0) { g_pm[pidx] = M; g_pl[pidx] = L; }
}

// ---------------------------------------------------------------------------
// Kernel 2: parallel finish (single PDL hop after pass1).  grid=(12, BB).
// Warp 0 of every block computes batch stats inline (2 chunks/lane + shfl).
//   blocks 0..7 : attention_weights slice (1 float4/thread)
//   blocks 8..11: ctx (16-way MLP) + 64 tanh-head outputs
// ---------------------------------------------------------------------------
__global__ void __launch_bounds__(256) finish_kernel(const float* __restrict__ hs,
                                                     const float* __restrict__ W2,
                                                     float* __restrict__ out) {
    const int q = blockIdx.x;
    const int b = blockIdx.y;
    const int tid = threadIdx.x;

    __shared__ float s_e[NCH];
    __shared__ float s_M, s_invL;
    __shared__ __align__(16) float x[2 * HH];   // [ctx | ht] (head blocks)

    // PDL prologue (independent of pass1): ht load + W2 prefetch for head blocks
    if (q >= 8) {
        x[HH + tid] = hs[(size_t)b * TT * HH + (size_t)(TT - 1) * HH + tid];
        const char* wbase = (const char*)(W2 + (size_t)((q - 8) * 64) * 2 * HH);
#pragma unroll
        for (int k = 0; k < 4; k++)
            prefetch_l2(wbase + (tid + k * 256) * 128);
    }

    gdc_wait();   // pass1 grid complete

    // inline stats: warp 0, 2 chunks per lane, shfl reductions
    if (tid < 32) {
        const float pm0 = g_pm[b * NCH + tid];
        const float pm1 = g_pm[b * NCH + 32 + tid];
        float M = fmaxf(pm0, pm1);
#pragma unroll
        for (int off = 16; off; off >>= 1)
            M = fmaxf(M, __shfl_xor_sync(0xffffffffu, M, off));
        const float e0 = __expf(pm0 - M);
        const float e1 = __expf(pm1 - M);
        float le = g_pl[b * NCH + tid] * e0 + g_pl[b * NCH + 32 + tid] * e1;
#pragma unroll
        for (int off = 16; off; off >>= 1)
            le += __shfl_xor_sync(0xffffffffu, le, off);
        s_e[tid] = e0;
        s_e[32 + tid] = e1;
        if (tid == 0) { s_M = M; s_invL = 1.f / le; }
    }
    __syncthreads();

    const float M = s_M;
    const float invL = s_invL;

    if (q < 8) {
        // ---- weights slice: 256 float4 per block, 8 blocks cover TT=8192 ----
        const int t4 = q * 256 + tid;
        float4 sc = ((const float4*)(g_scores + b * TT))[t4];
        float4 r;
        r.x = __expf(sc.x - M) * invL;
        r.y = __expf(sc.y - M) * invL;
        r.z = __expf(sc.z - M) * invL;
        r.w = __expf(sc.w - M) * invL;
        ((float4*)(out + BB * HH + b * TT))[t4] = r;
        return;
    }

    // ---- head quarter: outputs [p*64, p*64+64) ----
    const int p = q - 8;
    const int w = tid >> 5;
    const int lane = tid & 31;

    // ctx with 16 independent accumulators (4 serial memory rounds)
    {
        const float* pc = g_pc + (size_t)b * NCH * HH + tid;
        float C[16];
#pragma unroll
        for (int j = 0; j < 16; j++) C[j] = 0.f;
#pragma unroll
        for (int i = 0; i < NCH; i += 16) {
#pragma unroll
            for (int j = 0; j < 16; j++)
                C[j] += pc[(i + j) * HH] * s_e[i + j];
        }
        float Cs = 0.f;
#pragma unroll
        for (int j = 0; j < 16; j++) Cs += C[j];
        x[tid] = Cs * invL;
    }
    __syncthreads();

    const float4* x4 = (const float4*)x;        // 128 float4

    // 8 outputs per warp (two groups of 4), coalesced W2 reads
#pragma unroll
    for (int g = 0; g < 2; g++) {
        const int o0 = p * 64 + w * 8 + g * 4;
        float acc0 = 0.f, acc1 = 0.f, acc2 = 0.f, acc3 = 0.f;
        const float4* r0 = (const float4*)(W2 + (size_t)(o0 + 0) * 2 * HH);
        const float4* r1 = (const float4*)(W2 + (size_t)(o0 + 1) * 2 * HH);
        const float4* r2 = (const float4*)(W2 + (size_t)(o0 + 2) * 2 * HH);
        const float4* r3 = (const float4*)(W2 + (size_t)(o0 + 3) * 2 * HH);
#pragma unroll
        for (int k = 0; k < 4; k++) {
            const int j = lane + 32 * k;
            float4 xv = x4[j];
            float4 a0 = r0[j], a1 = r1[j], a2 = r2[j], a3 = r3[j];
            acc0 += a0.x * xv.x + a0.y * xv.y + a0.z * xv.z + a0.w * xv.w;
            acc1 += a1.x * xv.x + a1.y * xv.y + a1.z * xv.z + a1.w * xv.w;
            acc2 += a2.x * xv.x + a2.y * xv.y + a2.z * xv.z + a2.w * xv.w;
            acc3 += a3.x * xv.x + a3.y * xv.y + a3.z * xv.z + a3.w * xv.w;
        }
#pragma unroll
        for (int off = 16; off; off >>= 1) {
            acc0 += __shfl_xor_sync(0xffffffffu, acc0, off);
            acc1 += __shfl_xor_sync(0xffffffffu, acc1, off);
            acc2 += __shfl_xor_sync(0xffffffffu, acc2, off);
            acc3 += __shfl_xor_sync(0xffffffffu, acc3, off);
        }
        if (lane == 0) {
            out[b * HH + o0 + 0] = tanhf(acc0);
            out[b * HH + o0 + 1] = tanhf(acc1);
            out[b * HH + o0 + 2] = tanhf(acc2);
            out[b * HH + o0 + 3] = tanhf(acc3);
        }
    }
}

// ---------------------------------------------------------------------------
extern "C" void kernel_launch(void* const* d_in, const int* in_sizes, int n_in,
                              void* d_out, int out_size) {
    const float* hs = (const float*)d_in[0];   // (32, 8192, 256) f32
    const float* W1 = (const float*)d_in[1];   // (256, 256) f32
    const float* W2 = (const float*)d_in[2];   // (256, 512) f32
    float* out = (float*)d_out;

    static int smem_set = 0;
    if (!smem_set) {
        cudaFuncSetAttribute(pass1_kernel,
                             cudaFuncAttributeMaxDynamicSharedMemorySize,
                             NSTAGE * SBYTES);
        smem_set = 1;
    }

    cudaLaunchAttribute pdl[1];
    pdl[0].id = cudaLaunchAttributeProgrammaticStreamSerialization;
    pdl[0].val.programmaticStreamSerializationAllowed = 1;

    // Kernel 0: plain launch
    vpart_kernel<<<dim3(BB, 8), 256>>>(hs, W1);

    // Kernel 1: PDL secondary of vpart
    {
        cudaLaunchConfig_t cfg = {};
        cfg.gridDim = dim3(NCH, BB);
        cfg.blockDim = dim3(256);
        cfg.dynamicSmemBytes = NSTAGE * SBYTES;
        cfg.stream = 0;
        cfg.attrs = pdl;
        cfg.numAttrs = 1;
        cudaLaunchKernelEx(&cfg, pass1_kernel, hs);
    }

    // Kernel 2: PDL secondary of pass1
    {
        cudaLaunchConfig_t cfg = {};
        cfg.gridDim = dim3(12, BB);
        cfg.blockDim = dim3(256);
        cfg.stream = 0;
        cfg.attrs = pdl;
        cfg.numAttrs = 1;
        cudaLaunchKernelEx(&cfg, finish_kernel, hs, W2, out);
    }
}

// round 15
// speedup vs baseline: 1.0046x; 1.0046x over previous
#include <cuda_runtime.h>
#include <cstdint>

#define BB 32
#define TT 8192
#define HH 256
#define CHUNK 128
#define NCH (TT / CHUNK)          // 64 chunks per batch
#define NSTAGE 2
#define SROWS 32
#define NSTG (CHUNK / SROWS)      // 4 stages per CTA
#define SBYTES (SROWS * HH * 4)   // 32 KB per stage

// Scratch (__device__ globals: allocation-free rule)
__device__ float g_vp[BB * 8 * HH];       // split-K partials of v
__device__ float g_scores[BB * TT];       // raw logits
__device__ float g_pm[BB * NCH];          // per-chunk max
__device__ float g_pl[BB * NCH];          // per-chunk sum-exp
__device__ float g_pc[BB * NCH * HH];     // per-chunk partial context

// ---------------- PDL helpers ----------------
__device__ __forceinline__ void gdc_wait() {
    asm volatile("griddepcontrol.wait;" ::: "memory");
}
__device__ __forceinline__ void gdc_launch() {
    asm volatile("griddepcontrol.launch_dependents;");
}

// ---------------- mbarrier / bulk-async helpers ----------------
__device__ __forceinline__ uint32_t smem_u32(const void* p) {
    return (uint32_t)__cvta_generic_to_shared(p);
}
__device__ __forceinline__ void mbar_init(uint32_t a, uint32_t cnt) {
    asm volatile("mbarrier.init.shared.b64 [%0], %1;" :: "r"(a), "r"(cnt) : "memory");
}
__device__ __forceinline__ void mbar_expect_tx(uint32_t a, uint32_t bytes) {
    asm volatile("mbarrier.arrive.expect_tx.shared.b64 _, [%0], %1;"
                 :: "r"(a), "r"(bytes) : "memory");
}
__device__ __forceinline__ void mbar_arrive(uint32_t a) {
    asm volatile("mbarrier.arrive.shared.b64 _, [%0];" :: "r"(a) : "memory");
}
__device__ __forceinline__ void mbar_wait(uint32_t a, uint32_t parity) {
    asm volatile(
        "{\n\t.reg .pred P;\n\t"
        "LAB_%=:\n\t"
        "mbarrier.try_wait.parity.shared.b64 P, [%0], %1;\n\t"
        "@P bra.uni DONE_%=;\n\t"
        "bra.uni LAB_%=;\n\t"
        "DONE_%=:\n\t}"
        :: "r"(a), "r"(parity) : "memory");
}
__device__ __forceinline__ void bulk_g2s(uint32_t dst, const void* src,
                                         uint32_t bytes, uint32_t mbar) {
    asm volatile(
        "cp.async.bulk.shared::cluster.global.mbarrier::complete_tx::bytes "
        "[%0], [%1], %2, [%3];"
        :: "r"(dst), "l"(src), "r"(bytes), "r"(mbar) : "memory");
}
__device__ __forceinline__ void prefetch_l2(const void* p) {
    asm volatile("prefetch.global.L2 [%0];" :: "l"(p));
}

// ---------------------------------------------------------------------------
// Kernel 0: split-K partial of v.  grid=(BB, 8), block=256.
// Signals dependents immediately so pass1 can start its hs prefetches.
// ---------------------------------------------------------------------------
__global__ void __launch_bounds__(256) vpart_kernel(const float* __restrict__ hs,
                                                    const float* __restrict__ W1) {
    gdc_launch();
    const int b = blockIdx.x;
    const int s = blockIdx.y;
    const int h = threadIdx.x;
    __shared__ float ht[32];
    if (h < 32)
        ht[h] = hs[(size_t)b * TT * HH + (size_t)(TT - 1) * HH + s * 32 + h];
    __syncthreads();
    float acc = 0.f;
#pragma unroll
    for (int o = 0; o < 32; o++)
        acc += W1[(s * 32 + o) * HH + h] * ht[o];
    g_vp[(b * 8 + s) * HH + h] = acc;
}

// ---------------------------------------------------------------------------
// Kernel 1: bulk-async-staged fused score + online softmax + partial context.
// grid=(NCH, BB)=2048 CTAs, block=256 (8 warps), 2-stage 32 KB dynamic-smem
// ring.  Refill for stage s+2 is issued BEFORE the stage-s compute (the empty
// barrier completes as soon as all warps finish their loads), keeping the
// TMA pipe full while warps compute.
// ---------------------------------------------------------------------------
extern __shared__ __align__(16) float dynbuf[];   // NSTAGE * SROWS * HH floats

__global__ void __launch_bounds__(256) pass1_kernel(const float* __restrict__ hs) {
    __shared__ __align__(8) unsigned long long mb_full[NSTAGE];
    __shared__ __align__(8) unsigned long long mb_empty[NSTAGE];
    __shared__ float s_m[8], s_l[8];
    __shared__ float s_c[8][HH];                                  // 8 KB

    const int chunk = blockIdx.x;
    const int b = blockIdx.y;
    const int tid = threadIdx.x;
    const int w = tid >> 5;
    const int lane = tid & 31;

    uint32_t full_a[NSTAGE], empty_a[NSTAGE], buf_a[NSTAGE];
#pragma unroll
    for (int i = 0; i < NSTAGE; i++) {
        full_a[i] = smem_u32(&mb_full[i]);
        empty_a[i] = smem_u32(&mb_empty[i]);
        buf_a[i] = smem_u32(&dynbuf[i * SROWS * HH]);
    }

    if (tid == 0) {
#pragma unroll
        for (int i = 0; i < NSTAGE; i++) {
            mbar_init(full_a[i], 1);
            mbar_init(empty_a[i], 8);
        }
    }
    __syncthreads();

    const char* src =
        (const char*)(hs + ((size_t)b * TT + (size_t)chunk * CHUNK) * HH);

    if (tid == 0) {
#pragma unroll
        for (int i = 0; i < NSTAGE; i++) {
            mbar_expect_tx(full_a[i], SBYTES);
            bulk_g2s(buf_a[i], src + (size_t)i * SBYTES, SBYTES, full_a[i]);
        }
    }

    // Wait for vpart's grid (PDL) before touching g_vp.
    gdc_wait();

    // v slice for this lane = sum of the 8 split-K partials (L2-resident)
    const float4* vp4 = (const float4*)(g_vp) + (size_t)b * 8 * 64;
    float4 va = make_float4(0.f, 0.f, 0.f, 0.f);
    float4 vb = make_float4(0.f, 0.f, 0.f, 0.f);
#pragma unroll
    for (int s = 0; s < 8; s++) {
        float4 pa = vp4[s * 64 + lane];
        float4 pb = vp4[s * 64 + 32 + lane];
        va.x += pa.x; va.y += pa.y; va.z += pa.z; va.w += pa.w;
        vb.x += pb.x; vb.y += pb.y; vb.z += pb.z; vb.w += pb.w;
    }

    float m = -1e30f, l = 0.f;
    float4 ca = make_float4(0.f, 0.f, 0.f, 0.f);
    float4 cb = make_float4(0.f, 0.f, 0.f, 0.f);
    float* scores = g_scores + b * TT + chunk * CHUNK;

    for (int s = 0; s < NSTG; s++) {
        const int slot = s & (NSTAGE - 1);
        mbar_wait(full_a[slot], (s / NSTAGE) & 1);

        const float4* bf = (const float4*)(dynbuf + slot * SROWS * HH);
        const int r0 = w * 4;
        float4 x0a = bf[(r0 + 0) * 64 + lane], x0b = bf[(r0 + 0) * 64 + 32 + lane];
        float4 x1a = bf[(r0 + 1) * 64 + lane], x1b = bf[(r0 + 1) * 64 + 32 + lane];
        float4 x2a = bf[(r0 + 2) * 64 + lane], x2b = bf[(r0 + 2) * 64 + 32 + lane];
        float4 x3a = bf[(r0 + 3) * 64 + lane], x3b = bf[(r0 + 3) * 64 + 32 + lane];

        // Data in registers — release the stage to the producer NOW.
        if (lane == 0) mbar_arrive(empty_a[slot]);

        // Issue the refill for this slot BEFORE compute: the empty barrier
        // completes once all 8 warps finished their loads (~100 cy), so the
        // TMA goes out ~1 compute-phase earlier each stage.
        if (tid == 0 && s + NSTAGE < NSTG) {
            const int ns = s + NSTAGE;
            mbar_wait(empty_a[slot], ((ns / NSTAGE) - 1) & 1);
            mbar_expect_tx(full_a[slot], SBYTES);
            bulk_g2s(buf_a[slot], src + (size_t)ns * SBYTES, SBYTES, full_a[slot]);
        }

        float s0 = x0a.x * va.x + x0a.y * va.y + x0a.z * va.z + x0a.w * va.w
                 + x0b.x * vb.x + x0b.y * vb.y + x0b.z * vb.z + x0b.w * vb.w;
        float s1 = x1a.x * va.x + x1a.y * va.y + x1a.z * va.z + x1a.w * va.w
                 + x1b.x * vb.x + x1b.y * vb.y + x1b.z * vb.z + x1b.w * vb.w;
        float s2 = x2a.x * va.x + x2a.y * va.y + x2a.z * va.z + x2a.w * va.w
                 + x2b.x * vb.x + x2b.y * vb.y + x2b.z * vb.z + x2b.w * vb.w;
        float s3 = x3a.x * va.x + x3a.y * va.y + x3a.z * va.z + x3a.w * va.w
                 + x3b.x * vb.x + x3b.y * vb.y + x3b.z * vb.z + x3b.w * vb.w;
#pragma unroll
        for (int off = 16; off; off >>= 1) {
            s0 += __shfl_xor_sync(0xffffffffu, s0, off);
            s1 += __shfl_xor_sync(0xffffffffu, s1, off);
            s2 += __shfl_xor_sync(0xffffffffu, s2, off);
            s3 += __shfl_xor_sync(0xffffffffu, s3, off);
        }
        if (lane == 0)
            *(float4*)(scores + s * SROWS + r0) = make_float4(s0, s1, s2, s3);

        float mn = fmaxf(fmaxf(m, fmaxf(s0, s1)), fmaxf(s2, s3));
        float corr = __expf(m - mn);
        float p0 = __expf(s0 - mn);
        float p1 = __expf(s1 - mn);
        float p2 = __expf(s2 - mn);
        float p3 = __expf(s3 - mn);
        l = l * corr + p0 + p1 + p2 + p3;
        ca.x = ca.x * corr + p0 * x0a.x + p1 * x1a.x + p2 * x2a.x + p3 * x3a.x;
        ca.y = ca.y * corr + p0 * x0a.y + p1 * x1a.y + p2 * x2a.y + p3 * x3a.y;
        ca.z = ca.z * corr + p0 * x0a.z + p1 * x1a.z + p2 * x2a.z + p3 * x3a.z;
        ca.w = ca.w * corr + p0 * x0a.w + p1 * x1a.w + p2 * x2a.w + p3 * x3a.w;
        cb.x = cb.x * corr + p0 * x0b.x + p1 * x1b.x + p2 * x2b.x + p3 * x3b.x;
        cb.y = cb.y * corr + p0 * x0b.y + p1 * x1b.y + p2 * x2b.y + p3 * x3b.y;
        cb.z = cb.z * corr + p0 * x0b.z + p1 * x1b.z + p2 * x2b.z + p3 * x3b.z;
        cb.w = cb.w * corr + p0 * x0b.w + p1 * x1b.w + p2 * x2b.w + p3 * x3b.w;
        m = mn;
    }

    gdc_launch();   // streaming done — let finish start ramping

    if (lane == 0) { s_m[w] = m; s_l[w] = l; }
    s_c[w][lane * 4 + 0] = ca.x;
    s_c[w][lane * 4 + 1] = ca.y;
    s_c[w][lane * 4 + 2] = ca.z;
    s_c[w][lane * 4 + 3] = ca.w;
    s_c[w][128 + lane * 4 + 0] = cb.x;
    s_c[w][128 + lane * 4 + 1] = cb.y;
    s_c[w][128 + lane * 4 + 2] = cb.z;
    s_c[w][128 + lane * 4 + 3] = cb.w;
    __syncthreads();

    float M = -1e30f;
#pragma unroll
    for (int ww = 0; ww < 8; ww++) M = fmaxf(M, s_m[ww]);
    float L = 0.f, C = 0.f;
#pragma unroll
    for (int ww = 0; ww < 8; ww++) {
        float e = __expf(s_m[ww] - M);
        L += s_l[ww] * e;
        C += s_c[ww][tid] * e;
    }
    const int pidx = b * NCH + chunk;
    g_pc[pidx * HH + tid] = C;
    if (tid == 0) { g_pm[pidx] = M; g_pl[pidx] = L; }
}

// ---------------------------------------------------------------------------
// Kernel 2: parallel finish (single PDL hop after pass1).  grid=(12, BB).
// Warp 0 of every block computes batch stats inline (2 chunks/lane + shfl).
//   blocks 0..7 : attention_weights slice (1 float4/thread)
//   blocks 8..11: ctx (16-way MLP) + 64 tanh-head outputs
// ---------------------------------------------------------------------------
__global__ void __launch_bounds__(256) finish_kernel(const float* __restrict__ hs,
                                                     const float* __restrict__ W2,
                                                     float* __restrict__ out) {
    const int q = blockIdx.x;
    const int b = blockIdx.y;
    const int tid = threadIdx.x;

    __shared__ float s_e[NCH];
    __shared__ float s_M, s_invL;
    __shared__ __align__(16) float x[2 * HH];   // [ctx | ht] (head blocks)

    // PDL prologue (independent of pass1): ht load + W2 prefetch for head blocks
    if (q >= 8) {
        x[HH + tid] = hs[(size_t)b * TT * HH + (size_t)(TT - 1) * HH + tid];
        const char* wbase = (const char*)(W2 + (size_t)((q - 8) * 64) * 2 * HH);
#pragma unroll
        for (int k = 0; k < 4; k++)
            prefetch_l2(wbase + (tid + k * 256) * 128);
    }

    gdc_wait();   // pass1 grid complete

    // inline stats: warp 0, 2 chunks per lane, shfl reductions
    if (tid < 32) {
        const float pm0 = g_pm[b * NCH + tid];
        const float pm1 = g_pm[b * NCH + 32 + tid];
        float M = fmaxf(pm0, pm1);
#pragma unroll
        for (int off = 16; off; off >>= 1)
            M = fmaxf(M, __shfl_xor_sync(0xffffffffu, M, off));
        const float e0 = __expf(pm0 - M);
        const float e1 = __expf(pm1 - M);
        float le = g_pl[b * NCH + tid] * e0 + g_pl[b * NCH + 32 + tid] * e1;
#pragma unroll
        for (int off = 16; off; off >>= 1)
            le += __shfl_xor_sync(0xffffffffu, le, off);
        s_e[tid] = e0;
        s_e[32 + tid] = e1;
        if (tid == 0) { s_M = M; s_invL = 1.f / le; }
    }
    __syncthreads();

    const float M = s_M;
    const float invL = s_invL;

    if (q < 8) {
        // ---- weights slice: 256 float4 per block, 8 blocks cover TT=8192 ----
        const int t4 = q * 256 + tid;
        float4 sc = ((const float4*)(g_scores + b * TT))[t4];
        float4 r;
        r.x = __expf(sc.x - M) * invL;
        r.y = __expf(sc.y - M) * invL;
        r.z = __expf(sc.z - M) * invL;
        r.w = __expf(sc.w - M) * invL;
        ((float4*)(out + BB * HH + b * TT))[t4] = r;
        return;
    }

    // ---- head quarter: outputs [p*64, p*64+64) ----
    const int p = q - 8;
    const int w = tid >> 5;
    const int lane = tid & 31;

    // ctx with 16 independent accumulators (4 serial memory rounds)
    {
        const float* pc = g_pc + (size_t)b * NCH * HH + tid;
        float C[16];
#pragma unroll
        for (int j = 0; j < 16; j++) C[j] = 0.f;
#pragma unroll
        for (int i = 0; i < NCH; i += 16) {
#pragma unroll
            for (int j = 0; j < 16; j++)
                C[j] += pc[(i + j) * HH] * s_e[i + j];
        }
        float Cs = 0.f;
#pragma unroll
        for (int j = 0; j < 16; j++) Cs += C[j];
        x[tid] = Cs * invL;
    }
    __syncthreads();

    const float4* x4 = (const float4*)x;        // 128 float4

    // 8 outputs per warp (two groups of 4), coalesced W2 reads
#pragma unroll
    for (int g = 0; g < 2; g++) {
        const int o0 = p * 64 + w * 8 + g * 4;
        float acc0 = 0.f, acc1 = 0.f, acc2 = 0.f, acc3 = 0.f;
        const float4* r0 = (const float4*)(W2 + (size_t)(o0 + 0) * 2 * HH);
        const float4* r1 = (const float4*)(W2 + (size_t)(o0 + 1) * 2 * HH);
        const float4* r2 = (const float4*)(W2 + (size_t)(o0 + 2) * 2 * HH);
        const float4* r3 = (const float4*)(W2 + (size_t)(o0 + 3) * 2 * HH);
#pragma unroll
        for (int k = 0; k < 4; k++) {
            const int j = lane + 32 * k;
            float4 xv = x4[j];
            float4 a0 = r0[j], a1 = r1[j], a2 = r2[j], a3 = r3[j];
            acc0 += a0.x * xv.x + a0.y * xv.y + a0.z * xv.z + a0.w * xv.w;
            acc1 += a1.x * xv.x + a1.y * xv.y + a1.z * xv.z + a1.w * xv.w;
            acc2 += a2.x * xv.x + a2.y * xv.y + a2.z * xv.z + a2.w * xv.w;
            acc3 += a3.x * xv.x + a3.y * xv.y + a3.z * xv.z + a3.w * xv.w;
        }
#pragma unroll
        for (int off = 16; off; off >>= 1) {
            acc0 += __shfl_xor_sync(0xffffffffu, acc0, off);
            acc1 += __shfl_xor_sync(0xffffffffu, acc1, off);
            acc2 += __shfl_xor_sync(0xffffffffu, acc2, off);
            acc3 += __shfl_xor_sync(0xffffffffu, acc3, off);
        }
        if (lane == 0) {
            out[b * HH + o0 + 0] = tanhf(acc0);
            out[b * HH + o0 + 1] = tanhf(acc1);
            out[b * HH + o0 + 2] = tanhf(acc2);
            out[b * HH + o0 + 3] = tanhf(acc3);
        }
    }
}

// ---------------------------------------------------------------------------
extern "C" void kernel_launch(void* const* d_in, const int* in_sizes, int n_in,
                              void* d_out, int out_size) {
    const float* hs = (const float*)d_in[0];   // (32, 8192, 256) f32
    const float* W1 = (const float*)d_in[1];   // (256, 256) f32
    const float* W2 = (const float*)d_in[2];   // (256, 512) f32
    float* out = (float*)d_out;

    static int smem_set = 0;
    if (!smem_set) {
        cudaFuncSetAttribute(pass1_kernel,
                             cudaFuncAttributeMaxDynamicSharedMemorySize,
                             NSTAGE * SBYTES);
        smem_set = 1;
    }

    cudaLaunchAttribute pdl[1];
    pdl[0].id = cudaLaunchAttributeProgrammaticStreamSerialization;
    pdl[0].val.programmaticStreamSerializationAllowed = 1;

    // Kernel 0: plain launch
    vpart_kernel<<<dim3(BB, 8), 256>>>(hs, W1);

    // Kernel 1: PDL secondary of vpart
    {
        cudaLaunchConfig_t cfg = {};
        cfg.gridDim = dim3(NCH, BB);
        cfg.blockDim = dim3(256);
        cfg.dynamicSmemBytes = NSTAGE * SBYTES;
        cfg.stream = 0;
        cfg.attrs = pdl;
        cfg.numAttrs = 1;
        cudaLaunchKernelEx(&cfg, pass1_kernel, hs);
    }

    // Kernel 2: PDL secondary of pass1
    {
        cudaLaunchConfig_t cfg = {};
        cfg.gridDim = dim3(12, BB);
        cfg.blockDim = dim3(256);
        cfg.stream = 0;
        cfg.attrs = pdl;
        cfg.numAttrs = 1;
        cudaLaunchKernelEx(&cfg, finish_kernel, hs, W2, out);
    }
}